// round 4
// baseline (speedup 1.0000x reference)
#include <cuda_runtime.h>
#include <math_constants.h>

#define BB      8
#define HDIM    4096
#define NHEADS  32
#define HD      128
#define N3      12288          // 3*HDIM
#define KS1     32             // K-splits for qkv gemm
#define KC1     (HDIM / KS1)   // 128
#define KS2     64             // K-splits for proj gemm
#define KC2     (HDIM / KS2)   // 64
#define TSPLIT  8              // T-splits for flash decode

// ---------------- scratch (allocation-free) ----------------
__device__ __align__(16) float g_qkv_part[(size_t)KS1 * BB * N3];    // 12.6 MB
__device__ __align__(16) float g_qkv[BB * N3];
__device__ __align__(16) float g_proj_part[(size_t)KS2 * BB * HDIM]; // 8.4 MB
__device__ __align__(16) float g_ctx[BB * HDIM];
__device__ __align__(16) float g_pm[BB * NHEADS * TSPLIT];
__device__ __align__(16) float g_pl[BB * NHEADS * TSPLIT];
__device__ __align__(16) float g_pacc[BB * NHEADS * TSPLIT * HD];

// packed f32x2 fma (Blackwell): d = a*b + c on two lanes
__device__ __forceinline__ unsigned long long fma_f32x2(unsigned long long a,
                                                        unsigned long long b,
                                                        unsigned long long c) {
    unsigned long long d;
    asm("fma.rn.f32x2 %0, %1, %2, %3;" : "=l"(d) : "l"(a), "l"(b), "l"(c));
    return d;
}

// ---------------- split-K GEMV: part[split][b][col] = sum_k X[b][k]*W[k][col] ----------------
template <int N, int KCHUNK, bool PROJ>
__global__ __launch_bounds__(256) void gemm_partial_kernel(const float* __restrict__ Xin,
                                                           const float* __restrict__ W) {
    __shared__ unsigned long long xs[BB * KCHUNK];  // x value broadcast-packed into both f32 lanes
    const float* X = PROJ ? g_ctx : Xin;
    const int tid = threadIdx.x;
    const int k0  = blockIdx.y * KCHUNK;

    for (int i = tid; i < BB * KCHUNK; i += 256) {
        const int b = i / KCHUNK, kk = i - b * KCHUNK;
        const unsigned int u = __float_as_uint(X[b * HDIM + k0 + kk]);
        xs[i] = ((unsigned long long)u << 32) | u;
    }
    __syncthreads();

    const int col = blockIdx.x * 512 + tid * 2;
    unsigned long long acc[BB];
#pragma unroll
    for (int b = 0; b < BB; ++b) acc[b] = 0ull;  // bit pattern (0.f, 0.f)

    const unsigned long long* wp =
        reinterpret_cast<const unsigned long long*>(W + (size_t)k0 * N + col);
#pragma unroll 4
    for (int kk = 0; kk < KCHUNK; ++kk) {
        const unsigned long long w = *wp;
        wp += N / 2;
#pragma unroll
        for (int b = 0; b < BB; ++b)
            acc[b] = fma_f32x2(w, xs[b * KCHUNK + kk], acc[b]);
    }

    float* part = PROJ ? g_proj_part : g_qkv_part;
    const size_t base = (size_t)blockIdx.y * BB * N + col;
#pragma unroll
    for (int b = 0; b < BB; ++b)
        *reinterpret_cast<unsigned long long*>(part + base + (size_t)b * N) = acc[b];
}

// ---------------- deterministic split-K reduce + bias ----------------
template <int N, int NSPLIT, bool PROJ>
__global__ __launch_bounds__(256) void reduce_bias_kernel(const float* __restrict__ bias,
                                                          float* __restrict__ outp) {
    const int idx = blockIdx.x * 256 + threadIdx.x;
    if (idx >= BB * N) return;
    const int b = idx / N, j = idx - b * N;
    const float* part = PROJ ? g_proj_part : g_qkv_part;
    float s = bias[j];
#pragma unroll
    for (int p = 0; p < NSPLIT; ++p)
        s += part[((size_t)p * BB + b) * N + j];
    float* out = PROJ ? outp : g_qkv;
    out[idx] = s;
}

// ---------------- flash-decode attention partials ----------------
__global__ __launch_bounds__(128) void attn_partial_kernel(const float* __restrict__ ck,
                                                           const float* __restrict__ cv,
                                                           int P, int T, int chunk) {
    const int bh = blockIdx.x;
    const int b = bh >> 5, h = bh & (NHEADS - 1);
    const int split = blockIdx.y;
    const int t0 = split * chunk;
    const int t1 = min(t0 + chunk, T);

    __shared__ __align__(16) float qs[HD];
    __shared__ float wm[4], wl[4];
    __shared__ __align__(16) float wacc[4][HD];

    const int tid = threadIdx.x, wid = tid >> 5, lane = tid & 31;
    if (tid < HD) qs[tid] = g_qkv[b * N3 + h * HD + tid];
    __syncthreads();

    const float4 q4 = *reinterpret_cast<const float4*>(qs + lane * 4);
    const float scale = 0.08838834764831845f;  // 1/sqrt(128)

    float m = -CUDART_INF_F, l = 0.f;
    float ax = 0.f, ay = 0.f, az = 0.f, aw = 0.f;

    const size_t tstride = (size_t)BB * NHEADS * HD;
    const size_t bhoff = ((size_t)b * NHEADS + h) * HD + lane * 4;
    const float* knew = g_qkv + b * N3 + HDIM     + h * HD + lane * 4;
    const float* vnew = g_qkv + b * N3 + 2 * HDIM + h * HD + lane * 4;

#pragma unroll 2
    for (int t = t0 + wid; t < t1; t += 4) {
        const float *kp, *vp;
        if (t < P) {
            const size_t o = (size_t)t * tstride + bhoff;
            kp = ck + o; vp = cv + o;
        } else {
            kp = knew; vp = vnew;
        }
        const float4 k4 = *reinterpret_cast<const float4*>(kp);
        const float4 v4 = *reinterpret_cast<const float4*>(vp);

        float s = k4.x * q4.x;
        s = fmaf(k4.y, q4.y, s);
        s = fmaf(k4.z, q4.z, s);
        s = fmaf(k4.w, q4.w, s);
        s += __shfl_xor_sync(0xffffffffu, s, 16);
        s += __shfl_xor_sync(0xffffffffu, s, 8);
        s += __shfl_xor_sync(0xffffffffu, s, 4);
        s += __shfl_xor_sync(0xffffffffu, s, 2);
        s += __shfl_xor_sync(0xffffffffu, s, 1);
        s *= scale;

        const float nm   = fmaxf(m, s);
        const float corr = __expf(m - nm);   // first iter: exp(-inf)=0
        const float p    = __expf(s - nm);
        l  = fmaf(l,  corr, p);
        ax = fmaf(ax, corr, p * v4.x);
        ay = fmaf(ay, corr, p * v4.y);
        az = fmaf(az, corr, p * v4.z);
        aw = fmaf(aw, corr, p * v4.w);
        m = nm;
    }

    if (lane == 0) { wm[wid] = m; wl[wid] = l; }
    *reinterpret_cast<float4*>(&wacc[wid][lane * 4]) = make_float4(ax, ay, az, aw);
    __syncthreads();

    if (tid < HD) {
        const float M = fmaxf(fmaxf(wm[0], wm[1]), fmaxf(wm[2], wm[3]));
        float L = 0.f, A = 0.f;
#pragma unroll
        for (int w = 0; w < 4; ++w) {
            const float f = (wm[w] == -CUDART_INF_F) ? 0.f : __expf(wm[w] - M);
            L = fmaf(f, wl[w], L);
            A = fmaf(f, wacc[w][tid], A);
        }
        const int pi = bh * TSPLIT + split;
        g_pacc[pi * HD + tid] = A;
        if (tid == 0) { g_pm[pi] = M; g_pl[pi] = L; }
    }
}

// ---------------- combine T-splits -> context ----------------
__global__ __launch_bounds__(HD) void attn_combine_kernel() {
    const int bh = blockIdx.x;
    const int d  = threadIdx.x;
    float M = -CUDART_INF_F;
#pragma unroll
    for (int s = 0; s < TSPLIT; ++s) M = fmaxf(M, g_pm[bh * TSPLIT + s]);
    float L = 0.f, A = 0.f;
#pragma unroll
    for (int s = 0; s < TSPLIT; ++s) {
        const float mm = g_pm[bh * TSPLIT + s];
        const float f = (mm == -CUDART_INF_F) ? 0.f : __expf(mm - M);
        L = fmaf(f, g_pl[bh * TSPLIT + s], L);
        A = fmaf(f, g_pacc[(bh * TSPLIT + s) * HD + d], A);
    }
    const int b = bh >> 5, h = bh & (NHEADS - 1);
    g_ctx[b * HDIM + h * HD + d] = A / L;
}

// ---------------- launcher ----------------
extern "C" void kernel_launch(void* const* d_in, const int* in_sizes, int n_in,
                              void* d_out, int out_size) {
    const float* x     = (const float*)d_in[0];
    const float* ck    = (const float*)d_in[1];
    const float* cv    = (const float*)d_in[2];
    const float* Wqkv  = (const float*)d_in[3];
    const float* bqkv  = (const float*)d_in[4];
    const float* Wproj = (const float*)d_in[5];
    const float* bproj = (const float*)d_in[6];

    const int P = in_sizes[1] / (BB * NHEADS * HD);   // 2047
    const int T = P + 1;
    const int chunk = (T + TSPLIT - 1) / TSPLIT;

    // 1) qkv = x @ Wqkv (+ bqkv in reduce)
    gemm_partial_kernel<N3, KC1, false><<<dim3(N3 / 512, KS1), 256>>>(x, Wqkv);
    reduce_bias_kernel<N3, KS1, false><<<(BB * N3 + 255) / 256, 256>>>(bqkv, nullptr);

    // 2) flash-decode attention over cache + new token (no cache copy)
    attn_partial_kernel<<<dim3(BB * NHEADS, TSPLIT), 128>>>(ck, cv, P, T, chunk);
    attn_combine_kernel<<<BB * NHEADS, HD>>>();

    // 3) out = ctx @ Wproj + bproj
    gemm_partial_kernel<HDIM, KC2, true><<<dim3(HDIM / 512, KS2), 256>>>(nullptr, Wproj);
    reduce_bias_kernel<HDIM, KS2, true><<<(BB * HDIM + 255) / 256, 256>>>(bproj, (float*)d_out);
}

// round 5
// speedup vs baseline: 1.0003x; 1.0003x over previous
#include <cuda_runtime.h>
#include <math_constants.h>

#define BB      8
#define HDIM    4096
#define NHEADS  32
#define HD      128
#define N3      12288          // 3*HDIM
#define KS1     32             // K-splits for qkv gemm
#define KC1     (HDIM / KS1)   // 128
#define KS2     64             // K-splits for proj gemm
#define KC2     (HDIM / KS2)   // 64
#define TSPLIT  8              // T-splits for flash decode

// ---------------- scratch (allocation-free) ----------------
__device__ __align__(16) float g_qkv_part[(size_t)KS1 * BB * N3];    // 12.6 MB
__device__ __align__(16) float g_qkv[BB * N3];
__device__ __align__(16) float g_proj_part[(size_t)KS2 * BB * HDIM]; // 8.4 MB
__device__ __align__(16) float g_ctx[BB * HDIM];
__device__ __align__(16) float g_pm[BB * NHEADS * TSPLIT];
__device__ __align__(16) float g_pl[BB * NHEADS * TSPLIT];
__device__ __align__(16) float g_pacc[BB * NHEADS * TSPLIT * HD];

// packed f32x2 fma (Blackwell): d = a*b + c on two lanes
__device__ __forceinline__ unsigned long long fma_f32x2(unsigned long long a,
                                                        unsigned long long b,
                                                        unsigned long long c) {
    unsigned long long d;
    asm("fma.rn.f32x2 %0, %1, %2, %3;" : "=l"(d) : "l"(a), "l"(b), "l"(c));
    return d;
}

// ---------------- split-K GEMV: part[split][b][col] = sum_k X[b][k]*W[k][col] ----------------
template <int N, int KCHUNK, bool PROJ>
__global__ __launch_bounds__(256) void gemm_partial_kernel(const float* __restrict__ Xin,
                                                           const float* __restrict__ W) {
    __shared__ unsigned long long xs[BB * KCHUNK];  // x value broadcast-packed into both f32 lanes
    const float* X = PROJ ? g_ctx : Xin;
    const int tid = threadIdx.x;
    const int k0  = blockIdx.y * KCHUNK;

    for (int i = tid; i < BB * KCHUNK; i += 256) {
        const int b = i / KCHUNK, kk = i - b * KCHUNK;
        const unsigned int u = __float_as_uint(X[b * HDIM + k0 + kk]);
        xs[i] = ((unsigned long long)u << 32) | u;
    }
    __syncthreads();

    const int col = blockIdx.x * 512 + tid * 2;
    unsigned long long acc[BB];
#pragma unroll
    for (int b = 0; b < BB; ++b) acc[b] = 0ull;  // bit pattern (0.f, 0.f)

    const unsigned long long* wp =
        reinterpret_cast<const unsigned long long*>(W + (size_t)k0 * N + col);
#pragma unroll 4
    for (int kk = 0; kk < KCHUNK; ++kk) {
        const unsigned long long w = *wp;
        wp += N / 2;
#pragma unroll
        for (int b = 0; b < BB; ++b)
            acc[b] = fma_f32x2(w, xs[b * KCHUNK + kk], acc[b]);
    }

    float* part = PROJ ? g_proj_part : g_qkv_part;
    const size_t base = (size_t)blockIdx.y * BB * N + col;
#pragma unroll
    for (int b = 0; b < BB; ++b)
        *reinterpret_cast<unsigned long long*>(part + base + (size_t)b * N) = acc[b];
}

// ---------------- deterministic split-K reduce + bias ----------------
template <int N, int NSPLIT, bool PROJ>
__global__ __launch_bounds__(256) void reduce_bias_kernel(const float* __restrict__ bias,
                                                          float* __restrict__ outp) {
    const int idx = blockIdx.x * 256 + threadIdx.x;
    if (idx >= BB * N) return;
    const int b = idx / N, j = idx - b * N;
    const float* part = PROJ ? g_proj_part : g_qkv_part;
    float s = bias[j];
#pragma unroll
    for (int p = 0; p < NSPLIT; ++p)
        s += part[((size_t)p * BB + b) * N + j];
    float* out = PROJ ? outp : g_qkv;
    out[idx] = s;
}

// ---------------- flash-decode attention partials ----------------
__global__ __launch_bounds__(128) void attn_partial_kernel(const float* __restrict__ ck,
                                                           const float* __restrict__ cv,
                                                           int P, int T, int chunk) {
    const int bh = blockIdx.x;
    const int b = bh >> 5, h = bh & (NHEADS - 1);
    const int split = blockIdx.y;
    const int t0 = split * chunk;
    const int t1 = min(t0 + chunk, T);

    __shared__ __align__(16) float qs[HD];
    __shared__ float wm[4], wl[4];
    __shared__ __align__(16) float wacc[4][HD];

    const int tid = threadIdx.x, wid = tid >> 5, lane = tid & 31;
    if (tid < HD) qs[tid] = g_qkv[b * N3 + h * HD + tid];
    __syncthreads();

    const float4 q4 = *reinterpret_cast<const float4*>(qs + lane * 4);
    const float scale = 0.08838834764831845f;  // 1/sqrt(128)

    float m = -CUDART_INF_F, l = 0.f;
    float ax = 0.f, ay = 0.f, az = 0.f, aw = 0.f;

    const size_t tstride = (size_t)BB * NHEADS * HD;
    const size_t bhoff = ((size_t)b * NHEADS + h) * HD + lane * 4;
    const float* knew = g_qkv + b * N3 + HDIM     + h * HD + lane * 4;
    const float* vnew = g_qkv + b * N3 + 2 * HDIM + h * HD + lane * 4;

#pragma unroll 2
    for (int t = t0 + wid; t < t1; t += 4) {
        const float *kp, *vp;
        if (t < P) {
            const size_t o = (size_t)t * tstride + bhoff;
            kp = ck + o; vp = cv + o;
        } else {
            kp = knew; vp = vnew;
        }
        const float4 k4 = *reinterpret_cast<const float4*>(kp);
        const float4 v4 = *reinterpret_cast<const float4*>(vp);

        float s = k4.x * q4.x;
        s = fmaf(k4.y, q4.y, s);
        s = fmaf(k4.z, q4.z, s);
        s = fmaf(k4.w, q4.w, s);
        s += __shfl_xor_sync(0xffffffffu, s, 16);
        s += __shfl_xor_sync(0xffffffffu, s, 8);
        s += __shfl_xor_sync(0xffffffffu, s, 4);
        s += __shfl_xor_sync(0xffffffffu, s, 2);
        s += __shfl_xor_sync(0xffffffffu, s, 1);
        s *= scale;

        const float nm   = fmaxf(m, s);
        const float corr = __expf(m - nm);   // first iter: exp(-inf)=0
        const float p    = __expf(s - nm);
        l  = fmaf(l,  corr, p);
        ax = fmaf(ax, corr, p * v4.x);
        ay = fmaf(ay, corr, p * v4.y);
        az = fmaf(az, corr, p * v4.z);
        aw = fmaf(aw, corr, p * v4.w);
        m = nm;
    }

    if (lane == 0) { wm[wid] = m; wl[wid] = l; }
    *reinterpret_cast<float4*>(&wacc[wid][lane * 4]) = make_float4(ax, ay, az, aw);
    __syncthreads();

    if (tid < HD) {
        const float M = fmaxf(fmaxf(wm[0], wm[1]), fmaxf(wm[2], wm[3]));
        float L = 0.f, A = 0.f;
#pragma unroll
        for (int w = 0; w < 4; ++w) {
            const float f = (wm[w] == -CUDART_INF_F) ? 0.f : __expf(wm[w] - M);
            L = fmaf(f, wl[w], L);
            A = fmaf(f, wacc[w][tid], A);
        }
        const int pi = bh * TSPLIT + split;
        g_pacc[pi * HD + tid] = A;
        if (tid == 0) { g_pm[pi] = M; g_pl[pi] = L; }
    }
}

// ---------------- combine T-splits -> context ----------------
__global__ __launch_bounds__(HD) void attn_combine_kernel() {
    const int bh = blockIdx.x;
    const int d  = threadIdx.x;
    float M = -CUDART_INF_F;
#pragma unroll
    for (int s = 0; s < TSPLIT; ++s) M = fmaxf(M, g_pm[bh * TSPLIT + s]);
    float L = 0.f, A = 0.f;
#pragma unroll
    for (int s = 0; s < TSPLIT; ++s) {
        const float mm = g_pm[bh * TSPLIT + s];
        const float f = (mm == -CUDART_INF_F) ? 0.f : __expf(mm - M);
        L = fmaf(f, g_pl[bh * TSPLIT + s], L);
        A = fmaf(f, g_pacc[(bh * TSPLIT + s) * HD + d], A);
    }
    const int b = bh >> 5, h = bh & (NHEADS - 1);
    g_ctx[b * HDIM + h * HD + d] = A / L;
}

// ---------------- launcher ----------------
extern "C" void kernel_launch(void* const* d_in, const int* in_sizes, int n_in,
                              void* d_out, int out_size) {
    const float* x     = (const float*)d_in[0];
    const float* ck    = (const float*)d_in[1];
    const float* cv    = (const float*)d_in[2];
    const float* Wqkv  = (const float*)d_in[3];
    const float* bqkv  = (const float*)d_in[4];
    const float* Wproj = (const float*)d_in[5];
    const float* bproj = (const float*)d_in[6];

    const int P = in_sizes[1] / (BB * NHEADS * HD);   // 2047
    const int T = P + 1;
    const int chunk = (T + TSPLIT - 1) / TSPLIT;

    // 1) qkv = x @ Wqkv (+ bqkv in reduce)
    gemm_partial_kernel<N3, KC1, false><<<dim3(N3 / 512, KS1), 256>>>(x, Wqkv);
    reduce_bias_kernel<N3, KS1, false><<<(BB * N3 + 255) / 256, 256>>>(bqkv, nullptr);

    // 2) flash-decode attention over cache + new token (no cache copy)
    attn_partial_kernel<<<dim3(BB * NHEADS, TSPLIT), 128>>>(ck, cv, P, T, chunk);
    attn_combine_kernel<<<BB * NHEADS, HD>>>();

    // 3) out = ctx @ Wproj + bproj
    gemm_partial_kernel<HDIM, KC2, true><<<dim3(HDIM / 512, KS2), 256>>>(nullptr, Wproj);
    reduce_bias_kernel<HDIM, KS2, true><<<(BB * HDIM + 255) / 256, 256>>>(bproj, (float*)d_out);
}

// round 6
// speedup vs baseline: 1.0017x; 1.0014x over previous
#include <cuda_runtime.h>
#include <math_constants.h>

#define BB      8
#define HDIM    4096
#define NHEADS  32
#define HD      128
#define N3      12288          // 3*HDIM
#define KS1     32             // K-splits for qkv gemm
#define KC1     (HDIM / KS1)   // 128
#define KS2     64             // K-splits for proj gemm
#define KC2     (HDIM / KS2)   // 64
#define TSPLIT  8              // T-splits for flash decode

// ---------------- scratch (allocation-free) ----------------
__device__ __align__(16) float g_qkv_part[(size_t)KS1 * BB * N3];    // 12.6 MB
__device__ __align__(16) float g_qkv[BB * N3];
__device__ __align__(16) float g_proj_part[(size_t)KS2 * BB * HDIM]; // 8.4 MB
__device__ __align__(16) float g_ctx[BB * HDIM];
__device__ __align__(16) float g_pm[BB * NHEADS * TSPLIT];
__device__ __align__(16) float g_pl[BB * NHEADS * TSPLIT];
__device__ __align__(16) float g_pacc[BB * NHEADS * TSPLIT * HD];

// packed f32x2 fma (Blackwell): d = a*b + c on two lanes
__device__ __forceinline__ unsigned long long fma_f32x2(unsigned long long a,
                                                        unsigned long long b,
                                                        unsigned long long c) {
    unsigned long long d;
    asm("fma.rn.f32x2 %0, %1, %2, %3;" : "=l"(d) : "l"(a), "l"(b), "l"(c));
    return d;
}

// ---------------- split-K GEMV: part[split][b][col] = sum_k X[b][k]*W[k][col] ----------------
template <int N, int KCHUNK, bool PROJ>
__global__ __launch_bounds__(256) void gemm_partial_kernel(const float* __restrict__ Xin,
                                                           const float* __restrict__ W) {
    __shared__ unsigned long long xs[BB * KCHUNK];  // x value broadcast-packed into both f32 lanes
    const float* X = PROJ ? g_ctx : Xin;
    const int tid = threadIdx.x;
    const int k0  = blockIdx.y * KCHUNK;

    for (int i = tid; i < BB * KCHUNK; i += 256) {
        const int b = i / KCHUNK, kk = i - b * KCHUNK;
        const unsigned int u = __float_as_uint(X[b * HDIM + k0 + kk]);
        xs[i] = ((unsigned long long)u << 32) | u;
    }
    __syncthreads();

    const int col = blockIdx.x * 512 + tid * 2;
    unsigned long long acc[BB];
#pragma unroll
    for (int b = 0; b < BB; ++b) acc[b] = 0ull;  // bit pattern (0.f, 0.f)

    const unsigned long long* wp =
        reinterpret_cast<const unsigned long long*>(W + (size_t)k0 * N + col);
#pragma unroll 4
    for (int kk = 0; kk < KCHUNK; ++kk) {
        const unsigned long long w = *wp;
        wp += N / 2;
#pragma unroll
        for (int b = 0; b < BB; ++b)
            acc[b] = fma_f32x2(w, xs[b * KCHUNK + kk], acc[b]);
    }

    float* part = PROJ ? g_proj_part : g_qkv_part;
    const size_t base = (size_t)blockIdx.y * BB * N + col;
#pragma unroll
    for (int b = 0; b < BB; ++b)
        *reinterpret_cast<unsigned long long*>(part + base + (size_t)b * N) = acc[b];
}

// ---------------- deterministic split-K reduce + bias ----------------
template <int N, int NSPLIT, bool PROJ>
__global__ __launch_bounds__(256) void reduce_bias_kernel(const float* __restrict__ bias,
                                                          float* __restrict__ outp) {
    const int idx = blockIdx.x * 256 + threadIdx.x;
    if (idx >= BB * N) return;
    const int b = idx / N, j = idx - b * N;
    const float* part = PROJ ? g_proj_part : g_qkv_part;
    float s = bias[j];
#pragma unroll
    for (int p = 0; p < NSPLIT; ++p)
        s += part[((size_t)p * BB + b) * N + j];
    float* out = PROJ ? outp : g_qkv;
    out[idx] = s;
}

// ---------------- flash-decode attention partials ----------------
__global__ __launch_bounds__(128) void attn_partial_kernel(const float* __restrict__ ck,
                                                           const float* __restrict__ cv,
                                                           int P, int T, int chunk) {
    const int bh = blockIdx.x;
    const int b = bh >> 5, h = bh & (NHEADS - 1);
    const int split = blockIdx.y;
    const int t0 = split * chunk;
    const int t1 = min(t0 + chunk, T);

    __shared__ __align__(16) float qs[HD];
    __shared__ float wm[4], wl[4];
    __shared__ __align__(16) float wacc[4][HD];

    const int tid = threadIdx.x, wid = tid >> 5, lane = tid & 31;
    if (tid < HD) qs[tid] = g_qkv[b * N3 + h * HD + tid];
    __syncthreads();

    const float4 q4 = *reinterpret_cast<const float4*>(qs + lane * 4);
    const float scale = 0.08838834764831845f;  // 1/sqrt(128)

    float m = -CUDART_INF_F, l = 0.f;
    float ax = 0.f, ay = 0.f, az = 0.f, aw = 0.f;

    const size_t tstride = (size_t)BB * NHEADS * HD;
    const size_t bhoff = ((size_t)b * NHEADS + h) * HD + lane * 4;
    const float* knew = g_qkv + b * N3 + HDIM     + h * HD + lane * 4;
    const float* vnew = g_qkv + b * N3 + 2 * HDIM + h * HD + lane * 4;

#pragma unroll 2
    for (int t = t0 + wid; t < t1; t += 4) {
        const float *kp, *vp;
        if (t < P) {
            const size_t o = (size_t)t * tstride + bhoff;
            kp = ck + o; vp = cv + o;
        } else {
            kp = knew; vp = vnew;
        }
        const float4 k4 = *reinterpret_cast<const float4*>(kp);
        const float4 v4 = *reinterpret_cast<const float4*>(vp);

        float s = k4.x * q4.x;
        s = fmaf(k4.y, q4.y, s);
        s = fmaf(k4.z, q4.z, s);
        s = fmaf(k4.w, q4.w, s);
        s += __shfl_xor_sync(0xffffffffu, s, 16);
        s += __shfl_xor_sync(0xffffffffu, s, 8);
        s += __shfl_xor_sync(0xffffffffu, s, 4);
        s += __shfl_xor_sync(0xffffffffu, s, 2);
        s += __shfl_xor_sync(0xffffffffu, s, 1);
        s *= scale;

        const float nm   = fmaxf(m, s);
        const float corr = __expf(m - nm);   // first iter: exp(-inf)=0
        const float p    = __expf(s - nm);
        l  = fmaf(l,  corr, p);
        ax = fmaf(ax, corr, p * v4.x);
        ay = fmaf(ay, corr, p * v4.y);
        az = fmaf(az, corr, p * v4.z);
        aw = fmaf(aw, corr, p * v4.w);
        m = nm;
    }

    if (lane == 0) { wm[wid] = m; wl[wid] = l; }
    *reinterpret_cast<float4*>(&wacc[wid][lane * 4]) = make_float4(ax, ay, az, aw);
    __syncthreads();

    if (tid < HD) {
        const float M = fmaxf(fmaxf(wm[0], wm[1]), fmaxf(wm[2], wm[3]));
        float L = 0.f, A = 0.f;
#pragma unroll
        for (int w = 0; w < 4; ++w) {
            const float f = (wm[w] == -CUDART_INF_F) ? 0.f : __expf(wm[w] - M);
            L = fmaf(f, wl[w], L);
            A = fmaf(f, wacc[w][tid], A);
        }
        const int pi = bh * TSPLIT + split;
        g_pacc[pi * HD + tid] = A;
        if (tid == 0) { g_pm[pi] = M; g_pl[pi] = L; }
    }
}

// ---------------- combine T-splits -> context ----------------
__global__ __launch_bounds__(HD) void attn_combine_kernel() {
    const int bh = blockIdx.x;
    const int d  = threadIdx.x;
    float M = -CUDART_INF_F;
#pragma unroll
    for (int s = 0; s < TSPLIT; ++s) M = fmaxf(M, g_pm[bh * TSPLIT + s]);
    float L = 0.f, A = 0.f;
#pragma unroll
    for (int s = 0; s < TSPLIT; ++s) {
        const float mm = g_pm[bh * TSPLIT + s];
        const float f = (mm == -CUDART_INF_F) ? 0.f : __expf(mm - M);
        L = fmaf(f, g_pl[bh * TSPLIT + s], L);
        A = fmaf(f, g_pacc[(bh * TSPLIT + s) * HD + d], A);
    }
    const int b = bh >> 5, h = bh & (NHEADS - 1);
    g_ctx[b * HDIM + h * HD + d] = A / L;
}

// ---------------- launcher ----------------
extern "C" void kernel_launch(void* const* d_in, const int* in_sizes, int n_in,
                              void* d_out, int out_size) {
    const float* x     = (const float*)d_in[0];
    const float* ck    = (const float*)d_in[1];
    const float* cv    = (const float*)d_in[2];
    const float* Wqkv  = (const float*)d_in[3];
    const float* bqkv  = (const float*)d_in[4];
    const float* Wproj = (const float*)d_in[5];
    const float* bproj = (const float*)d_in[6];

    const int P = in_sizes[1] / (BB * NHEADS * HD);   // 2047
    const int T = P + 1;
    const int chunk = (T + TSPLIT - 1) / TSPLIT;

    // 1) qkv = x @ Wqkv (+ bqkv in reduce)
    gemm_partial_kernel<N3, KC1, false><<<dim3(N3 / 512, KS1), 256>>>(x, Wqkv);
    reduce_bias_kernel<N3, KS1, false><<<(BB * N3 + 255) / 256, 256>>>(bqkv, nullptr);

    // 2) flash-decode attention over cache + new token (no cache copy)
    attn_partial_kernel<<<dim3(BB * NHEADS, TSPLIT), 128>>>(ck, cv, P, T, chunk);
    attn_combine_kernel<<<BB * NHEADS, HD>>>();

    // 3) out = ctx @ Wproj + bproj
    gemm_partial_kernel<HDIM, KC2, true><<<dim3(HDIM / 512, KS2), 256>>>(nullptr, Wproj);
    reduce_bias_kernel<HDIM, KS2, true><<<(BB * HDIM + 255) / 256, 256>>>(bproj, (float*)d_out);
}